// round 4
// baseline (speedup 1.0000x reference)
#include <cuda_runtime.h>
#include <math.h>

#define DIM   2048
#define NH    16
#define NKV   4
#define HD    128
#define BB    2
#define SL    2048
#define MROWS (BB*SL)                 // 4096
#define QKV_N ((NH + 2*NKV)*HD)       // 3072

// ---------------- scratch (static device globals; no allocations) -----------
__device__ float g_qkv [MROWS * QKV_N];        // [m][3072]
__device__ float g_q   [BB*NH *SL*HD];         // [b][h][s][d]
__device__ float g_k   [BB*NKV*SL*HD];         // [b][kv][s][d]
__device__ float g_v   [BB*NKV*SL*HD];         // [b][kv][s][d]
__device__ float g_attn[MROWS * DIM];          // [m][h*128+d]

// ---------------------------------------------------------------------------
// C = A * B^T.  A[M][K] row-major, B[N][K] row-major, C[M][N] row-major.
// Requires M%128==0, N%128==0, K%16==0. 128x128 tile, 8x8 microtile, 256 thr.
// ---------------------------------------------------------------------------
__global__ __launch_bounds__(256, 2)
void sgemm_nt(const float* __restrict__ A, const float* __restrict__ B,
              float* __restrict__ C, int M, int N, int K) {
    __shared__ float As[16][128];
    __shared__ float Bs[16][128];
    const int tid = threadIdx.x;
    const int tx = tid & 15;        // n micro
    const int ty = tid >> 4;        // m micro
    const int m0 = blockIdx.y * 128;
    const int n0 = blockIdx.x * 128;
    const float* Ab = A + (size_t)m0 * K;
    const float* Bb = B + (size_t)n0 * K;

    float acc[8][8];
#pragma unroll
    for (int i = 0; i < 8; i++)
#pragma unroll
        for (int j = 0; j < 8; j++) acc[i][j] = 0.0f;

    for (int k0 = 0; k0 < K; k0 += 16) {
#pragma unroll
        for (int it = 0; it < 2; it++) {
            int idx = tid + it * 256;           // 0..511 float4 slots
            int r  = idx >> 2;                  // 0..127 tile row
            int kq = (idx & 3) << 2;            // 0,4,8,12
            float4 av = *(const float4*)(Ab + (size_t)r * K + k0 + kq);
            float4 bv = *(const float4*)(Bb + (size_t)r * K + k0 + kq);
            As[kq + 0][r] = av.x; As[kq + 1][r] = av.y;
            As[kq + 2][r] = av.z; As[kq + 3][r] = av.w;
            Bs[kq + 0][r] = bv.x; Bs[kq + 1][r] = bv.y;
            Bs[kq + 2][r] = bv.z; Bs[kq + 3][r] = bv.w;
        }
        __syncthreads();
#pragma unroll
        for (int kk = 0; kk < 16; kk++) {
            float a[8], b[8];
            *(float4*)&a[0] = *(const float4*)&As[kk][ty * 8];
            *(float4*)&a[4] = *(const float4*)&As[kk][ty * 8 + 4];
            *(float4*)&b[0] = *(const float4*)&Bs[kk][tx * 8];
            *(float4*)&b[4] = *(const float4*)&Bs[kk][tx * 8 + 4];
#pragma unroll
            for (int i = 0; i < 8; i++)
#pragma unroll
                for (int j = 0; j < 8; j++)
                    acc[i][j] = fmaf(a[i], b[j], acc[i][j]);
        }
        __syncthreads();
    }

#pragma unroll
    for (int i = 0; i < 8; i++) {
        float* Crow = C + (size_t)(m0 + ty * 8 + i) * N + n0 + tx * 8;
        *(float4*)&Crow[0] = make_float4(acc[i][0], acc[i][1], acc[i][2], acc[i][3]);
        *(float4*)&Crow[4] = make_float4(acc[i][4], acc[i][5], acc[i][6], acc[i][7]);
    }
}

// ---------------------------------------------------------------------------
// Per-(token, head) RMSNorm + RoPE. One block of 128 threads per head vector.
// Heads: 0..15 -> Q, 16..19 -> K, 20..23 -> V (copy only).
// ---------------------------------------------------------------------------
__global__ __launch_bounds__(128)
void norm_rope(const float* __restrict__ qnw, const float* __restrict__ knw,
               const float* __restrict__ fcos, const float* __restrict__ fsin) {
    __shared__ float wsum[4];
    __shared__ float rbc;
    const int hh = blockIdx.x % 24;
    const int m  = blockIdx.x / 24;
    const int b  = m / SL;
    const int s  = m % SL;
    const int d  = threadIdx.x;

    float v = g_qkv[(size_t)m * QKV_N + hh * HD + d];

    if (hh < 20) {
        float ssq = v * v;
#pragma unroll
        for (int o = 16; o > 0; o >>= 1)
            ssq += __shfl_xor_sync(0xffffffffu, ssq, o);
        if ((d & 31) == 0) wsum[d >> 5] = ssq;
        __syncthreads();
        if (d == 0)
            rbc = rsqrtf((wsum[0] + wsum[1] + wsum[2] + wsum[3]) * (1.0f / HD)
                         + 1.1920929e-07f);
        __syncthreads();
        const float* w = (hh < NH) ? qnw : knw;
        float xn = v * rbc * w[d];
        float part = __shfl_xor_sync(0xffffffffu, xn, 1);
        float rot  = (d & 1) ? part : -part;     // rot[2i]=-x[2i+1], rot[2i+1]=x[2i]
        float o = xn * fcos[s * HD + d] + rot * fsin[s * HD + d];
        if (hh < NH)
            g_q[(((size_t)b * NH  + hh)      * SL + s) * HD + d] = o;
        else
            g_k[(((size_t)b * NKV + (hh-16)) * SL + s) * HD + d] = o;
    } else {
        g_v[(((size_t)b * NKV + (hh-20)) * SL + s) * HD + d] = v;
    }
}

// ---------------------------------------------------------------------------
// Flash attention, fp32. Q-tile 64 x 128, K/V-tile 32 x 128, 256 threads.
// S computed into smem, online softmax in exp2 domain (log2e*scale folded
// into Q), PV accumulated in registers (8 rows x 4 cols per thread).
// ---------------------------------------------------------------------------
#define QT   64
#define KT   32
#define KPAD 132
#define SPAD 33
#define FLASH_SMEM ((QT*HD + KT*KPAD + KT*HD + QT*SPAD + 3*QT) * 4)

__global__ __launch_bounds__(256, 2)
void flash_attn() {
    extern __shared__ float sm[];
    float* Qs   = sm;                    // 64*128
    float* Ks   = Qs + QT * HD;          // 32*132 (padded rows)
    float* Vs   = Ks + KT * KPAD;        // 32*128
    float* Ps   = Vs + KT * HD;          // 64*33
    float* rowm = Ps + QT * SPAD;        // 64
    float* rowl = rowm + QT;             // 64
    float* rowa = rowl + QT;             // 64

    const int tid = threadIdx.x;
    const int qt = blockIdx.x, h = blockIdx.y, b = blockIdx.z;
    const int kvh = h >> 2;                              // GQA: 4 q heads / kv head

    const float* Qg = g_q + (((size_t)b * NH  + h  ) * SL + qt * QT) * HD;
    const float* Kg = g_k + (((size_t)b * NKV + kvh) * SL) * HD;
    const float* Vg = g_v + (((size_t)b * NKV + kvh) * SL) * HD;

    const float qscale = 1.4426950408889634f * rsqrtf((float)HD);

    // load Q (pre-scaled by log2e/sqrt(d))
#pragma unroll
    for (int it = 0; it < 8; it++) {
        int idx = tid + it * 256;                 // 0..2047 float4
        int r = idx >> 5, dq = (idx & 31) << 2;
        float4 v = *(const float4*)(Qg + (size_t)r * HD + dq);
        v.x *= qscale; v.y *= qscale; v.z *= qscale; v.w *= qscale;
        *(float4*)&Qs[r * HD + dq] = v;
    }
    if (tid < QT) { rowm[tid] = -INFINITY; rowl[tid] = 0.0f; }

    float acc[8][4];
#pragma unroll
    for (int i = 0; i < 8; i++)
#pragma unroll
        for (int j = 0; j < 4; j++) acc[i][j] = 0.0f;

    const int tx = tid & 15, ty = tid >> 4;       // S-GEMM map: 4 rows x 2 cols
    const int rowg = tid >> 5, lane = tid & 31;   // PV map: 8 rows x 4 cols

    for (int kt = 0; kt < SL / KT; kt++) {
        __syncthreads();   // prev PV done before overwriting Ks/Vs
#pragma unroll
        for (int it = 0; it < 4; it++) {
            int idx = tid + it * 256;             // 0..1023 float4
            int r = idx >> 5, dq = (idx & 31) << 2;
            *(float4*)&Ks[r * KPAD + dq] =
                *(const float4*)(Kg + (size_t)(kt * KT + r) * HD + dq);
            *(float4*)&Vs[r * HD + dq] =
                *(const float4*)(Vg + (size_t)(kt * KT + r) * HD + dq);
        }
        __syncthreads();

        // ---- S = Qs * Ks^T (scaled) ----
        {
            float s00=0,s01=0,s10=0,s11=0,s20=0,s21=0,s30=0,s31=0;
#pragma unroll 4
            for (int d0 = 0; d0 < HD; d0 += 4) {
                float4 k0v = *(const float4*)&Ks[(2 * tx    ) * KPAD + d0];
                float4 k1v = *(const float4*)&Ks[(2 * tx + 1) * KPAD + d0];
                float4 q0 = *(const float4*)&Qs[(4 * ty + 0) * HD + d0];
                float4 q1 = *(const float4*)&Qs[(4 * ty + 1) * HD + d0];
                float4 q2 = *(const float4*)&Qs[(4 * ty + 2) * HD + d0];
                float4 q3 = *(const float4*)&Qs[(4 * ty + 3) * HD + d0];
                s00 += q0.x*k0v.x + q0.y*k0v.y + q0.z*k0v.z + q0.w*k0v.w;
                s01 += q0.x*k1v.x + q0.y*k1v.y + q0.z*k1v.z + q0.w*k1v.w;
                s10 += q1.x*k0v.x + q1.y*k0v.y + q1.z*k0v.z + q1.w*k0v.w;
                s11 += q1.x*k1v.x + q1.y*k1v.y + q1.z*k1v.z + q1.w*k1v.w;
                s20 += q2.x*k0v.x + q2.y*k0v.y + q2.z*k0v.z + q2.w*k0v.w;
                s21 += q2.x*k1v.x + q2.y*k1v.y + q2.z*k1v.z + q2.w*k1v.w;
                s30 += q3.x*k0v.x + q3.y*k0v.y + q3.z*k0v.z + q3.w*k0v.w;
                s31 += q3.x*k1v.x + q3.y*k1v.y + q3.z*k1v.z + q3.w*k1v.w;
            }
            Ps[(4*ty+0)*SPAD + 2*tx] = s00;  Ps[(4*ty+0)*SPAD + 2*tx+1] = s01;
            Ps[(4*ty+1)*SPAD + 2*tx] = s10;  Ps[(4*ty+1)*SPAD + 2*tx+1] = s11;
            Ps[(4*ty+2)*SPAD + 2*tx] = s20;  Ps[(4*ty+2)*SPAD + 2*tx+1] = s21;
            Ps[(4*ty+3)*SPAD + 2*tx] = s30;  Ps[(4*ty+3)*SPAD + 2*tx+1] = s31;
        }
        __syncthreads();

        // ---- phase A: row max + alpha (exp2 domain) ----
        if (tid < QT) {
            float mo = rowm[tid], tm = -INFINITY;
#pragma unroll
            for (int c = 0; c < KT; c++) tm = fmaxf(tm, Ps[tid * SPAD + c]);
            float mn = fmaxf(mo, tm);
            rowa[tid] = exp2f(mo - mn);
            rowm[tid] = mn;
        }
        __syncthreads();

        // ---- phase B: exponentiate own S elements in place ----
#pragma unroll
        for (int i = 0; i < 4; i++) {
            float mr = rowm[4 * ty + i];
            float* p = &Ps[(4 * ty + i) * SPAD + 2 * tx];
            p[0] = exp2f(p[0] - mr);
            p[1] = exp2f(p[1] - mr);
        }
        __syncthreads();

        // ---- phase C: row sums (warps 0-1), read-only on Ps ----
        if (tid < QT) {
            float sum = 0.0f;
#pragma unroll
            for (int c = 0; c < KT; c++) sum += Ps[tid * SPAD + c];
            rowl[tid] = rowl[tid] * rowa[tid] + sum;
        }

        // ---- PV: rescale O by alpha, accumulate P*V ----
#pragma unroll
        for (int i = 0; i < 8; i++) {
            float al = rowa[rowg * 8 + i];
            acc[i][0] *= al; acc[i][1] *= al; acc[i][2] *= al; acc[i][3] *= al;
        }
#pragma unroll 4
        for (int c = 0; c < KT; c++) {
            float4 v4 = *(const float4*)&Vs[c * HD + lane * 4];
#pragma unroll
            for (int i = 0; i < 8; i++) {
                float p = Ps[(rowg * 8 + i) * SPAD + c];
                acc[i][0] = fmaf(p, v4.x, acc[i][0]);
                acc[i][1] = fmaf(p, v4.y, acc[i][1]);
                acc[i][2] = fmaf(p, v4.z, acc[i][2]);
                acc[i][3] = fmaf(p, v4.w, acc[i][3]);
            }
        }
    }
    __syncthreads();

    // ---- normalize + write [b, s, h*128+d] ----
#pragma unroll
    for (int i = 0; i < 8; i++) {
        int r = rowg * 8 + i;
        float inv = 1.0f / rowl[r];
        float* o = g_attn + ((size_t)b * SL + qt * QT + r) * DIM + h * HD + lane * 4;
        *(float4*)o = make_float4(acc[i][0] * inv, acc[i][1] * inv,
                                  acc[i][2] * inv, acc[i][3] * inv);
    }
}

// ---------------------------------------------------------------------------
extern "C" void kernel_launch(void* const* d_in, const int* in_sizes, int n_in,
                              void* d_out, int out_size) {
    const float* x    = (const float*)d_in[0];
    const float* wqkv = (const float*)d_in[1];
    const float* wo   = (const float*)d_in[2];
    const float* qnw  = (const float*)d_in[3];
    const float* knw  = (const float*)d_in[4];
    const float* fcos = (const float*)d_in[5];
    const float* fsin = (const float*)d_in[6];
    float* out = (float*)d_out;

    void *p_qkv = nullptr, *p_attn = nullptr;
    cudaGetSymbolAddress(&p_qkv,  g_qkv);
    cudaGetSymbolAddress(&p_attn, g_attn);

    // Idempotent, called every time (no static guards — harness rule).
    // Not a stream op, so it does not interfere with graph capture.
    cudaFuncSetAttribute(flash_attn,
                         cudaFuncAttributeMaxDynamicSharedMemorySize,
                         FLASH_SMEM);

    // 1) QKV projection: [4096,3072] = x[4096,2048] * wqkv^T
    sgemm_nt<<<dim3(QKV_N / 128, MROWS / 128), 256>>>(
        x, wqkv, (float*)p_qkv, MROWS, QKV_N, DIM);

    // 2) RMSNorm + RoPE -> g_q / g_k / g_v
    norm_rope<<<MROWS * 24, 128>>>(qnw, knw, fcos, fsin);

    // 3) Flash attention -> g_attn
    flash_attn<<<dim3(SL / QT, NH, BB), 256, FLASH_SMEM>>>();

    // 4) Output projection: out[4096,2048] = attn * wo^T
    sgemm_nt<<<dim3(DIM / 128, MROWS / 128), 256>>>(
        (const float*)p_attn, wo, out, MROWS, DIM, DIM);
}

// round 5
// speedup vs baseline: 1.4587x; 1.4587x over previous
#include <cuda_runtime.h>
#include <math.h>
#include <stdint.h>

#define DIM   2048
#define NH    16
#define NKV   4
#define HD    128
#define BB    2
#define SL    2048
#define MROWS (BB*SL)                 // 4096
#define QKV_N ((NH + 2*NKV)*HD)       // 3072

// ---------------- scratch (static device globals; no allocations) -----------
__device__ float g_qkv [MROWS * QKV_N];        // [m][3072]
__device__ float g_q   [BB*NH *SL*HD];         // [b][h][s][d]
__device__ float g_k   [BB*NKV*SL*HD];         // [b][kv][s][d]
__device__ float g_v   [BB*NKV*SL*HD];         // [b][kv][s][d]
__device__ float g_attn[MROWS * DIM];          // [m][h*128+d]

__device__ __forceinline__ float to_tf32(float x) {
    float r;
    asm("cvt.rna.tf32.f32 %0, %1;" : "=f"(r) : "f"(x));
    return r;
}

// ---------------------------------------------------------------------------
// C = A * B^T via tf32 mma.sync.m16n8k8.  A[M][K], B[N][K] row-major.
// 128x128 tile, 8 warps (each 64x32), K-stage 16, swizzled smem.
// ---------------------------------------------------------------------------
#define SPITCH 136

__global__ __launch_bounds__(256, 2)
void sgemm_tf32(const float* __restrict__ A, const float* __restrict__ B,
                float* __restrict__ C, int M, int N, int K) {
    __shared__ float As[16][SPITCH];
    __shared__ float Bs[16][SPITCH];

    const int tid  = threadIdx.x;
    const int lane = tid & 31;
    const int warp = tid >> 5;
    const int wm   = warp & 1;          // 0/1 -> 64-row half
    const int wn   = warp >> 1;         // 0..3 -> 32-col quarter
    const int gid  = lane >> 2;         // 0..7
    const int tig  = lane & 3;          // 0..3

    const int m0 = blockIdx.y * 128;
    const int n0 = blockIdx.x * 128;
    const float* Ab = A + (size_t)m0 * K;
    const float* Bb = B + (size_t)n0 * K;

    // loader mapping: thread loads rows lr and lr+64 at k offset lk (float4)
    const int lr   = tid >> 2;           // 0..63
    const int lk   = (tid & 3) << 2;     // 0,4,8,12
    const int lkey = (tid & 3) << 3;     // swizzle xor = (lk/4)*8
    const int ca0  = lr        ^ lkey;
    const int ca1  = (lr + 64) ^ lkey;

    float c[4][4][4] = {};

    const int nstage = K / 16;
    float4 ra0, ra1, rb0, rb1;

    // prefetch stage 0
    ra0 = *(const float4*)(Ab + (size_t)lr        * K + lk);
    ra1 = *(const float4*)(Ab + (size_t)(lr + 64) * K + lk);
    rb0 = *(const float4*)(Bb + (size_t)lr        * K + lk);
    rb1 = *(const float4*)(Bb + (size_t)(lr + 64) * K + lk);

    for (int s = 0; s < nstage; s++) {
        __syncthreads();
        As[lk + 0][ca0] = to_tf32(ra0.x); As[lk + 1][ca0] = to_tf32(ra0.y);
        As[lk + 2][ca0] = to_tf32(ra0.z); As[lk + 3][ca0] = to_tf32(ra0.w);
        As[lk + 0][ca1] = to_tf32(ra1.x); As[lk + 1][ca1] = to_tf32(ra1.y);
        As[lk + 2][ca1] = to_tf32(ra1.z); As[lk + 3][ca1] = to_tf32(ra1.w);
        Bs[lk + 0][ca0] = to_tf32(rb0.x); Bs[lk + 1][ca0] = to_tf32(rb0.y);
        Bs[lk + 2][ca0] = to_tf32(rb0.z); Bs[lk + 3][ca0] = to_tf32(rb0.w);
        Bs[lk + 0][ca1] = to_tf32(rb1.x); Bs[lk + 1][ca1] = to_tf32(rb1.y);
        Bs[lk + 2][ca1] = to_tf32(rb1.z); Bs[lk + 3][ca1] = to_tf32(rb1.w);
        __syncthreads();

        if (s + 1 < nstage) {
            int k0 = (s + 1) * 16;
            ra0 = *(const float4*)(Ab + (size_t)lr        * K + k0 + lk);
            ra1 = *(const float4*)(Ab + (size_t)(lr + 64) * K + k0 + lk);
            rb0 = *(const float4*)(Bb + (size_t)lr        * K + k0 + lk);
            rb1 = *(const float4*)(Bb + (size_t)(lr + 64) * K + k0 + lk);
        }

#pragma unroll
        for (int kk = 0; kk < 16; kk += 8) {
            const int k_lo = kk + tig;
            const int k_hi = kk + tig + 4;
            const int x_lo = ((k_lo >> 2) & 3) << 3;   // swizzle xor
            const int x_hi = ((k_hi >> 2) & 3) << 3;

            uint32_t a[4][4], b[4][2];
#pragma unroll
            for (int f = 0; f < 4; f++) {
                int row = wm * 64 + f * 16 + gid;
                a[f][0] = __float_as_uint(As[k_lo][ row      ^ x_lo]);
                a[f][1] = __float_as_uint(As[k_lo][(row + 8) ^ x_lo]);
                a[f][2] = __float_as_uint(As[k_hi][ row      ^ x_hi]);
                a[f][3] = __float_as_uint(As[k_hi][(row + 8) ^ x_hi]);
            }
#pragma unroll
            for (int g = 0; g < 4; g++) {
                int col = wn * 32 + g * 8 + gid;
                b[g][0] = __float_as_uint(Bs[k_lo][col ^ x_lo]);
                b[g][1] = __float_as_uint(Bs[k_hi][col ^ x_hi]);
            }
#pragma unroll
            for (int f = 0; f < 4; f++)
#pragma unroll
                for (int g = 0; g < 4; g++) {
                    asm volatile(
                        "mma.sync.aligned.m16n8k8.row.col.f32.tf32.tf32.f32 "
                        "{%0,%1,%2,%3},{%4,%5,%6,%7},{%8,%9},{%0,%1,%2,%3};"
                        : "+f"(c[f][g][0]), "+f"(c[f][g][1]),
                          "+f"(c[f][g][2]), "+f"(c[f][g][3])
                        : "r"(a[f][0]), "r"(a[f][1]), "r"(a[f][2]), "r"(a[f][3]),
                          "r"(b[g][0]), "r"(b[g][1]));
                }
        }
    }

#pragma unroll
    for (int f = 0; f < 4; f++) {
        int row = m0 + wm * 64 + f * 16 + gid;
#pragma unroll
        for (int g = 0; g < 4; g++) {
            int col = n0 + wn * 32 + g * 8 + 2 * tig;
            *(float2*)&C[(size_t)row * N + col] =
                make_float2(c[f][g][0], c[f][g][1]);
            *(float2*)&C[(size_t)(row + 8) * N + col] =
                make_float2(c[f][g][2], c[f][g][3]);
        }
    }
}

// ---------------------------------------------------------------------------
// Per-(token, head) RMSNorm + RoPE. One block of 128 threads per head vector.
// Heads: 0..15 -> Q, 16..19 -> K, 20..23 -> V (copy only).
// ---------------------------------------------------------------------------
__global__ __launch_bounds__(128)
void norm_rope(const float* __restrict__ qnw, const float* __restrict__ knw,
               const float* __restrict__ fcos, const float* __restrict__ fsin) {
    __shared__ float wsum[4];
    __shared__ float rbc;
    const int hh = blockIdx.x % 24;
    const int m  = blockIdx.x / 24;
    const int b  = m / SL;
    const int s  = m % SL;
    const int d  = threadIdx.x;

    float v = g_qkv[(size_t)m * QKV_N + hh * HD + d];

    if (hh < 20) {
        float ssq = v * v;
#pragma unroll
        for (int o = 16; o > 0; o >>= 1)
            ssq += __shfl_xor_sync(0xffffffffu, ssq, o);
        if ((d & 31) == 0) wsum[d >> 5] = ssq;
        __syncthreads();
        if (d == 0)
            rbc = rsqrtf((wsum[0] + wsum[1] + wsum[2] + wsum[3]) * (1.0f / HD)
                         + 1.1920929e-07f);
        __syncthreads();
        const float* w = (hh < NH) ? qnw : knw;
        float xn = v * rbc * w[d];
        float part = __shfl_xor_sync(0xffffffffu, xn, 1);
        float rot  = (d & 1) ? part : -part;
        float o = xn * fcos[s * HD + d] + rot * fsin[s * HD + d];
        if (hh < NH)
            g_q[(((size_t)b * NH  + hh)      * SL + s) * HD + d] = o;
        else
            g_k[(((size_t)b * NKV + (hh-16)) * SL + s) * HD + d] = o;
    } else {
        g_v[(((size_t)b * NKV + (hh-20)) * SL + s) * HD + d] = v;
    }
}

// ---------------------------------------------------------------------------
// Flash attention, fp32. Q-tile 64 x 128, K/V-tile 32 x 128, 256 threads.
// ---------------------------------------------------------------------------
#define QT   64
#define KT   32
#define KPAD 132
#define SPAD 33
#define FLASH_SMEM ((QT*HD + KT*KPAD + KT*HD + QT*SPAD + 3*QT) * 4)

__global__ __launch_bounds__(256, 2)
void flash_attn() {
    extern __shared__ float sm[];
    float* Qs   = sm;                    // 64*128
    float* Ks   = Qs + QT * HD;          // 32*132
    float* Vs   = Ks + KT * KPAD;        // 32*128
    float* Ps   = Vs + KT * HD;          // 64*33
    float* rowm = Ps + QT * SPAD;        // 64
    float* rowl = rowm + QT;             // 64
    float* rowa = rowl + QT;             // 64

    const int tid = threadIdx.x;
    const int qt = blockIdx.x, h = blockIdx.y, b = blockIdx.z;
    const int kvh = h >> 2;

    const float* Qg = g_q + (((size_t)b * NH  + h  ) * SL + qt * QT) * HD;
    const float* Kg = g_k + (((size_t)b * NKV + kvh) * SL) * HD;
    const float* Vg = g_v + (((size_t)b * NKV + kvh) * SL) * HD;

    const float qscale = 1.4426950408889634f * rsqrtf((float)HD);

#pragma unroll
    for (int it = 0; it < 8; it++) {
        int idx = tid + it * 256;
        int r = idx >> 5, dq = (idx & 31) << 2;
        float4 v = *(const float4*)(Qg + (size_t)r * HD + dq);
        v.x *= qscale; v.y *= qscale; v.z *= qscale; v.w *= qscale;
        *(float4*)&Qs[r * HD + dq] = v;
    }
    if (tid < QT) { rowm[tid] = -INFINITY; rowl[tid] = 0.0f; }

    float acc[8][4];
#pragma unroll
    for (int i = 0; i < 8; i++)
#pragma unroll
        for (int j = 0; j < 4; j++) acc[i][j] = 0.0f;

    const int tx = tid & 15, ty = tid >> 4;
    const int rowg = tid >> 5, lane = tid & 31;

    for (int kt = 0; kt < SL / KT; kt++) {
        __syncthreads();
#pragma unroll
        for (int it = 0; it < 4; it++) {
            int idx = tid + it * 256;
            int r = idx >> 5, dq = (idx & 31) << 2;
            *(float4*)&Ks[r * KPAD + dq] =
                *(const float4*)(Kg + (size_t)(kt * KT + r) * HD + dq);
            *(float4*)&Vs[r * HD + dq] =
                *(const float4*)(Vg + (size_t)(kt * KT + r) * HD + dq);
        }
        __syncthreads();

        {
            float s00=0,s01=0,s10=0,s11=0,s20=0,s21=0,s30=0,s31=0;
#pragma unroll 4
            for (int d0 = 0; d0 < HD; d0 += 4) {
                float4 k0v = *(const float4*)&Ks[(2 * tx    ) * KPAD + d0];
                float4 k1v = *(const float4*)&Ks[(2 * tx + 1) * KPAD + d0];
                float4 q0 = *(const float4*)&Qs[(4 * ty + 0) * HD + d0];
                float4 q1 = *(const float4*)&Qs[(4 * ty + 1) * HD + d0];
                float4 q2 = *(const float4*)&Qs[(4 * ty + 2) * HD + d0];
                float4 q3 = *(const float4*)&Qs[(4 * ty + 3) * HD + d0];
                s00 += q0.x*k0v.x + q0.y*k0v.y + q0.z*k0v.z + q0.w*k0v.w;
                s01 += q0.x*k1v.x + q0.y*k1v.y + q0.z*k1v.z + q0.w*k1v.w;
                s10 += q1.x*k0v.x + q1.y*k0v.y + q1.z*k0v.z + q1.w*k0v.w;
                s11 += q1.x*k1v.x + q1.y*k1v.y + q1.z*k1v.z + q1.w*k1v.w;
                s20 += q2.x*k0v.x + q2.y*k0v.y + q2.z*k0v.z + q2.w*k0v.w;
                s21 += q2.x*k1v.x + q2.y*k1v.y + q2.z*k1v.z + q2.w*k1v.w;
                s30 += q3.x*k0v.x + q3.y*k0v.y + q3.z*k0v.z + q3.w*k0v.w;
                s31 += q3.x*k1v.x + q3.y*k1v.y + q3.z*k1v.z + q3.w*k1v.w;
            }
            Ps[(4*ty+0)*SPAD + 2*tx] = s00;  Ps[(4*ty+0)*SPAD + 2*tx+1] = s01;
            Ps[(4*ty+1)*SPAD + 2*tx] = s10;  Ps[(4*ty+1)*SPAD + 2*tx+1] = s11;
            Ps[(4*ty+2)*SPAD + 2*tx] = s20;  Ps[(4*ty+2)*SPAD + 2*tx+1] = s21;
            Ps[(4*ty+3)*SPAD + 2*tx] = s30;  Ps[(4*ty+3)*SPAD + 2*tx+1] = s31;
        }
        __syncthreads();

        if (tid < QT) {
            float mo = rowm[tid], tm = -INFINITY;
#pragma unroll
            for (int c = 0; c < KT; c++) tm = fmaxf(tm, Ps[tid * SPAD + c]);
            float mn = fmaxf(mo, tm);
            rowa[tid] = exp2f(mo - mn);
            rowm[tid] = mn;
        }
        __syncthreads();

#pragma unroll
        for (int i = 0; i < 4; i++) {
            float mr = rowm[4 * ty + i];
            float* p = &Ps[(4 * ty + i) * SPAD + 2 * tx];
            p[0] = exp2f(p[0] - mr);
            p[1] = exp2f(p[1] - mr);
        }
        __syncthreads();

        if (tid < QT) {
            float sum = 0.0f;
#pragma unroll
            for (int c = 0; c < KT; c++) sum += Ps[tid * SPAD + c];
            rowl[tid] = rowl[tid] * rowa[tid] + sum;
        }

#pragma unroll
        for (int i = 0; i < 8; i++) {
            float al = rowa[rowg * 8 + i];
            acc[i][0] *= al; acc[i][1] *= al; acc[i][2] *= al; acc[i][3] *= al;
        }
#pragma unroll 4
        for (int c = 0; c < KT; c++) {
            float4 v4 = *(const float4*)&Vs[c * HD + lane * 4];
#pragma unroll
            for (int i = 0; i < 8; i++) {
                float p = Ps[(rowg * 8 + i) * SPAD + c];
                acc[i][0] = fmaf(p, v4.x, acc[i][0]);
                acc[i][1] = fmaf(p, v4.y, acc[i][1]);
                acc[i][2] = fmaf(p, v4.z, acc[i][2]);
                acc[i][3] = fmaf(p, v4.w, acc[i][3]);
            }
        }
    }
    __syncthreads();

#pragma unroll
    for (int i = 0; i < 8; i++) {
        int r = rowg * 8 + i;
        float inv = 1.0f / rowl[r];
        float* o = g_attn + ((size_t)b * SL + qt * QT + r) * DIM + h * HD + lane * 4;
        *(float4*)o = make_float4(acc[i][0] * inv, acc[i][1] * inv,
                                  acc[i][2] * inv, acc[i][3] * inv);
    }
}

// ---------------------------------------------------------------------------
extern "C" void kernel_launch(void* const* d_in, const int* in_sizes, int n_in,
                              void* d_out, int out_size) {
    const float* x    = (const float*)d_in[0];
    const float* wqkv = (const float*)d_in[1];
    const float* wo   = (const float*)d_in[2];
    const float* qnw  = (const float*)d_in[3];
    const float* knw  = (const float*)d_in[4];
    const float* fcos = (const float*)d_in[5];
    const float* fsin = (const float*)d_in[6];
    float* out = (float*)d_out;

    void *p_qkv = nullptr, *p_attn = nullptr;
    cudaGetSymbolAddress(&p_qkv,  g_qkv);
    cudaGetSymbolAddress(&p_attn, g_attn);

    cudaFuncSetAttribute(flash_attn,
                         cudaFuncAttributeMaxDynamicSharedMemorySize,
                         FLASH_SMEM);

    // 1) QKV projection (tf32 tensor): [4096,3072] = x * wqkv^T
    sgemm_tf32<<<dim3(QKV_N / 128, MROWS / 128), 256>>>(
        x, wqkv, (float*)p_qkv, MROWS, QKV_N, DIM);

    // 2) RMSNorm + RoPE -> g_q / g_k / g_v
    norm_rope<<<MROWS * 24, 128>>>(qnw, knw, fcos, fsin);

    // 3) Flash attention -> g_attn
    flash_attn<<<dim3(SL / QT, NH, BB), 256, FLASH_SMEM>>>();

    // 4) Output projection (tf32 tensor): out = attn * wo^T
    sgemm_tf32<<<dim3(DIM / 128, MROWS / 128), 256>>>(
        (const float*)p_attn, wo, out, MROWS, DIM, DIM);
}

// round 6
// speedup vs baseline: 3.3810x; 2.3179x over previous
#include <cuda_runtime.h>
#include <math.h>
#include <stdint.h>

#define DIM   2048
#define NH    16
#define NKV   4
#define HD    128
#define BB    2
#define SL    2048
#define MROWS (BB*SL)                 // 4096
#define QKV_N ((NH + 2*NKV)*HD)       // 3072

// ---------------- scratch (static device globals; no allocations) -----------
__device__ float g_qkv [MROWS * QKV_N];        // [m][3072]
__device__ float g_q   [BB*NH *SL*HD];         // [b][h][s][d]
__device__ float g_k   [BB*NKV*SL*HD];         // [b][kv][s][d]
__device__ float g_v   [BB*NKV*SL*HD];         // [b][kv][s][d]
__device__ float g_attn[MROWS * DIM];          // [m][h*128+d]

__device__ __forceinline__ float to_tf32(float x) {
    float r;
    asm("cvt.rna.tf32.f32 %0, %1;" : "=f"(r) : "f"(x));
    return r;
}

__device__ __forceinline__ void mma_tf32(float c[4],
                                         uint32_t a0, uint32_t a1,
                                         uint32_t a2, uint32_t a3,
                                         uint32_t b0, uint32_t b1) {
    asm volatile(
        "mma.sync.aligned.m16n8k8.row.col.f32.tf32.tf32.f32 "
        "{%0,%1,%2,%3},{%4,%5,%6,%7},{%8,%9},{%0,%1,%2,%3};"
        : "+f"(c[0]), "+f"(c[1]), "+f"(c[2]), "+f"(c[3])
        : "r"(a0), "r"(a1), "r"(a2), "r"(a3), "r"(b0), "r"(b1));
}

// ---------------------------------------------------------------------------
// C = A * B^T via tf32 mma.sync.m16n8k8.  A[M][K], B[N][K] row-major.
// 128x128 tile, 8 warps (each 64x32), K-stage 16, swizzled smem.
// ---------------------------------------------------------------------------
#define SPITCH 136

__global__ __launch_bounds__(256, 2)
void sgemm_tf32(const float* __restrict__ A, const float* __restrict__ B,
                float* __restrict__ C, int M, int N, int K) {
    __shared__ float As[16][SPITCH];
    __shared__ float Bs[16][SPITCH];

    const int tid  = threadIdx.x;
    const int lane = tid & 31;
    const int warp = tid >> 5;
    const int wm   = warp & 1;
    const int wn   = warp >> 1;
    const int gid  = lane >> 2;
    const int tig  = lane & 3;

    const int m0 = blockIdx.y * 128;
    const int n0 = blockIdx.x * 128;
    const float* Ab = A + (size_t)m0 * K;
    const float* Bb = B + (size_t)n0 * K;

    const int lr   = tid >> 2;
    const int lk   = (tid & 3) << 2;
    const int lkey = (tid & 3) << 3;
    const int ca0  = lr        ^ lkey;
    const int ca1  = (lr + 64) ^ lkey;

    float c[4][4][4] = {};

    const int nstage = K / 16;
    float4 ra0, ra1, rb0, rb1;

    ra0 = *(const float4*)(Ab + (size_t)lr        * K + lk);
    ra1 = *(const float4*)(Ab + (size_t)(lr + 64) * K + lk);
    rb0 = *(const float4*)(Bb + (size_t)lr        * K + lk);
    rb1 = *(const float4*)(Bb + (size_t)(lr + 64) * K + lk);

    for (int s = 0; s < nstage; s++) {
        __syncthreads();
        As[lk + 0][ca0] = to_tf32(ra0.x); As[lk + 1][ca0] = to_tf32(ra0.y);
        As[lk + 2][ca0] = to_tf32(ra0.z); As[lk + 3][ca0] = to_tf32(ra0.w);
        As[lk + 0][ca1] = to_tf32(ra1.x); As[lk + 1][ca1] = to_tf32(ra1.y);
        As[lk + 2][ca1] = to_tf32(ra1.z); As[lk + 3][ca1] = to_tf32(ra1.w);
        Bs[lk + 0][ca0] = to_tf32(rb0.x); Bs[lk + 1][ca0] = to_tf32(rb0.y);
        Bs[lk + 2][ca0] = to_tf32(rb0.z); Bs[lk + 3][ca0] = to_tf32(rb0.w);
        Bs[lk + 0][ca1] = to_tf32(rb1.x); Bs[lk + 1][ca1] = to_tf32(rb1.y);
        Bs[lk + 2][ca1] = to_tf32(rb1.z); Bs[lk + 3][ca1] = to_tf32(rb1.w);
        __syncthreads();

        if (s + 1 < nstage) {
            int k0 = (s + 1) * 16;
            ra0 = *(const float4*)(Ab + (size_t)lr        * K + k0 + lk);
            ra1 = *(const float4*)(Ab + (size_t)(lr + 64) * K + k0 + lk);
            rb0 = *(const float4*)(Bb + (size_t)lr        * K + k0 + lk);
            rb1 = *(const float4*)(Bb + (size_t)(lr + 64) * K + k0 + lk);
        }

#pragma unroll
        for (int kk = 0; kk < 16; kk += 8) {
            const int k_lo = kk + tig;
            const int k_hi = kk + tig + 4;
            const int x_lo = ((k_lo >> 2) & 3) << 3;
            const int x_hi = ((k_hi >> 2) & 3) << 3;

            uint32_t a[4][4], b[4][2];
#pragma unroll
            for (int f = 0; f < 4; f++) {
                int row = wm * 64 + f * 16 + gid;
                a[f][0] = __float_as_uint(As[k_lo][ row      ^ x_lo]);
                a[f][1] = __float_as_uint(As[k_lo][(row + 8) ^ x_lo]);
                a[f][2] = __float_as_uint(As[k_hi][ row      ^ x_hi]);
                a[f][3] = __float_as_uint(As[k_hi][(row + 8) ^ x_hi]);
            }
#pragma unroll
            for (int g = 0; g < 4; g++) {
                int col = wn * 32 + g * 8 + gid;
                b[g][0] = __float_as_uint(Bs[k_lo][col ^ x_lo]);
                b[g][1] = __float_as_uint(Bs[k_hi][col ^ x_hi]);
            }
#pragma unroll
            for (int f = 0; f < 4; f++)
#pragma unroll
                for (int g = 0; g < 4; g++)
                    mma_tf32(c[f][g], a[f][0], a[f][1], a[f][2], a[f][3],
                             b[g][0], b[g][1]);
        }
    }

#pragma unroll
    for (int f = 0; f < 4; f++) {
        int row = m0 + wm * 64 + f * 16 + gid;
#pragma unroll
        for (int g = 0; g < 4; g++) {
            int col = n0 + wn * 32 + g * 8 + 2 * tig;
            *(float2*)&C[(size_t)row * N + col] =
                make_float2(c[f][g][0], c[f][g][1]);
            *(float2*)&C[(size_t)(row + 8) * N + col] =
                make_float2(c[f][g][2], c[f][g][3]);
        }
    }
}

// ---------------------------------------------------------------------------
// Per-(token, head) RMSNorm + RoPE.
// ---------------------------------------------------------------------------
__global__ __launch_bounds__(128)
void norm_rope(const float* __restrict__ qnw, const float* __restrict__ knw,
               const float* __restrict__ fcos, const float* __restrict__ fsin) {
    __shared__ float wsum[4];
    __shared__ float rbc;
    const int hh = blockIdx.x % 24;
    const int m  = blockIdx.x / 24;
    const int b  = m / SL;
    const int s  = m % SL;
    const int d  = threadIdx.x;

    float v = g_qkv[(size_t)m * QKV_N + hh * HD + d];

    if (hh < 20) {
        float ssq = v * v;
#pragma unroll
        for (int o = 16; o > 0; o >>= 1)
            ssq += __shfl_xor_sync(0xffffffffu, ssq, o);
        if ((d & 31) == 0) wsum[d >> 5] = ssq;
        __syncthreads();
        if (d == 0)
            rbc = rsqrtf((wsum[0] + wsum[1] + wsum[2] + wsum[3]) * (1.0f / HD)
                         + 1.1920929e-07f);
        __syncthreads();
        const float* w = (hh < NH) ? qnw : knw;
        float xn = v * rbc * w[d];
        float part = __shfl_xor_sync(0xffffffffu, xn, 1);
        float rot  = (d & 1) ? part : -part;
        float o = xn * fcos[s * HD + d] + rot * fsin[s * HD + d];
        if (hh < NH)
            g_q[(((size_t)b * NH  + hh)      * SL + s) * HD + d] = o;
        else
            g_k[(((size_t)b * NKV + (hh-16)) * SL + s) * HD + d] = o;
    } else {
        g_v[(((size_t)b * NKV + (hh-20)) * SL + s) * HD + d] = v;
    }
}

// ---------------------------------------------------------------------------
// Flash attention, tf32 tensor cores. QT=128 per block (8 warps x 16 rows),
// KT=64. Q a-frags register-resident; P->A frag conversion via warp shuffles.
// K smem pitch 132 (bank = 4*gid+tig distinct), V pitch 136 (8*tig+gid).
// ---------------------------------------------------------------------------
#define FQT  128
#define FKT  64
#define KP   132
#define VP   136
#define FLASH_SMEM ((FKT*KP + FKT*VP) * 4)    // 68608 B; Q staging aliases it

__global__ __launch_bounds__(256)
void flash_tf32() {
    extern __shared__ float sm[];
    float* Ks = sm;                 // 64 x 132
    float* Vs = sm + FKT * KP;      // 64 x 136
    float* Qb = sm;                 // alias: 128 x 132 staging (16896 <= 17152)

    const int tid  = threadIdx.x;
    const int lane = tid & 31;
    const int warp = tid >> 5;
    const int gid  = lane >> 2;
    const int tig  = lane & 3;
    const int wq   = warp * 16;

    const int qt = blockIdx.x, h = blockIdx.y, b = blockIdx.z;
    const int kvh = h >> 2;

    const float* Qg = g_q + (((size_t)b * NH  + h  ) * SL + qt * FQT) * HD;
    const float* Kg = g_k + (((size_t)b * NKV + kvh) * SL) * HD;
    const float* Vg = g_v + (((size_t)b * NKV + kvh) * SL) * HD;

    const float qscale = 1.4426950408889634f * rsqrtf((float)HD);

    // ---- stage Q (scaled, tf32) into aliased smem, then cache frags ----
#pragma unroll
    for (int it = 0; it < 16; it++) {
        int idx = tid + it * 256;               // 0..4095 float4 slots
        int r = idx >> 5, c = (idx & 31) << 2;
        float4 v = *(const float4*)(Qg + (size_t)r * HD + c);
        Qb[r * KP + c + 0] = to_tf32(v.x * qscale);
        Qb[r * KP + c + 1] = to_tf32(v.y * qscale);
        Qb[r * KP + c + 2] = to_tf32(v.z * qscale);
        Qb[r * KP + c + 3] = to_tf32(v.w * qscale);
    }
    __syncthreads();

    uint32_t qa[16][4];
#pragma unroll
    for (int ks = 0; ks < 16; ks++) {
        int base = (wq + gid) * KP + 8 * ks + tig;
        qa[ks][0] = __float_as_uint(Qb[base]);
        qa[ks][1] = __float_as_uint(Qb[base + 8 * KP]);
        qa[ks][2] = __float_as_uint(Qb[base + 4]);
        qa[ks][3] = __float_as_uint(Qb[base + 8 * KP + 4]);
    }

    float c[16][4] = {};          // O accum: rows gid,gid+8; cols 8*j2+2tig..
    float m0 = -INFINITY, m1 = -INFINITY, l0 = 0.0f, l1 = 0.0f;

    const int srcA = (gid << 2) + (tig >> 1);
    const int srcB = srcA + 2;
    const bool odd = (tig & 1) != 0;

    for (int kt = 0; kt < SL / FKT; kt++) {
        __syncthreads();          // prior compute done (and Q frags read)
#pragma unroll
        for (int it = 0; it < 8; it++) {
            int idx = tid + it * 256;           // 0..2047 float4
            int r = idx >> 5, cc = (idx & 31) << 2;
            float4 kv = *(const float4*)(Kg + (size_t)(kt * FKT + r) * HD + cc);
            float4 vv = *(const float4*)(Vg + (size_t)(kt * FKT + r) * HD + cc);
            Ks[r * KP + cc + 0] = to_tf32(kv.x);
            Ks[r * KP + cc + 1] = to_tf32(kv.y);
            Ks[r * KP + cc + 2] = to_tf32(kv.z);
            Ks[r * KP + cc + 3] = to_tf32(kv.w);
            Vs[r * VP + cc + 0] = to_tf32(vv.x);
            Vs[r * VP + cc + 1] = to_tf32(vv.y);
            Vs[r * VP + cc + 2] = to_tf32(vv.z);
            Vs[r * VP + cc + 3] = to_tf32(vv.w);
        }
        __syncthreads();

        // ---- S = Q * K^T (64 cols), fp32 accum ----
        float sc[8][4] = {};
#pragma unroll
        for (int ks = 0; ks < 16; ks++) {
#pragma unroll
            for (int j = 0; j < 8; j++) {
                uint32_t b0 = __float_as_uint(Ks[(8 * j + gid) * KP + 8 * ks + tig]);
                uint32_t b1 = __float_as_uint(Ks[(8 * j + gid) * KP + 8 * ks + tig + 4]);
                mma_tf32(sc[j], qa[ks][0], qa[ks][1], qa[ks][2], qa[ks][3], b0, b1);
            }
        }

        // ---- online softmax (rows gid and gid+8, quad-reduced) ----
        float t0 = -INFINITY, t1 = -INFINITY;
#pragma unroll
        for (int j = 0; j < 8; j++) {
            t0 = fmaxf(t0, fmaxf(sc[j][0], sc[j][1]));
            t1 = fmaxf(t1, fmaxf(sc[j][2], sc[j][3]));
        }
        t0 = fmaxf(t0, __shfl_xor_sync(0xffffffffu, t0, 1));
        t0 = fmaxf(t0, __shfl_xor_sync(0xffffffffu, t0, 2));
        t1 = fmaxf(t1, __shfl_xor_sync(0xffffffffu, t1, 1));
        t1 = fmaxf(t1, __shfl_xor_sync(0xffffffffu, t1, 2));
        float mn0 = fmaxf(m0, t0), mn1 = fmaxf(m1, t1);
        float al0 = exp2f(m0 - mn0), al1 = exp2f(m1 - mn1);
        m0 = mn0; m1 = mn1;

        float s0 = 0.0f, s1 = 0.0f;
#pragma unroll
        for (int j = 0; j < 8; j++) {
            float p0 = exp2f(sc[j][0] - mn0);
            float p1 = exp2f(sc[j][1] - mn0);
            float p2 = exp2f(sc[j][2] - mn1);
            float p3 = exp2f(sc[j][3] - mn1);
            s0 += p0 + p1; s1 += p2 + p3;
            sc[j][0] = to_tf32(p0); sc[j][1] = to_tf32(p1);
            sc[j][2] = to_tf32(p2); sc[j][3] = to_tf32(p3);
        }
        s0 += __shfl_xor_sync(0xffffffffu, s0, 1);
        s0 += __shfl_xor_sync(0xffffffffu, s0, 2);
        s1 += __shfl_xor_sync(0xffffffffu, s1, 1);
        s1 += __shfl_xor_sync(0xffffffffu, s1, 2);
        l0 = l0 * al0 + s0;
        l1 = l1 * al1 + s1;

#pragma unroll
        for (int j2 = 0; j2 < 16; j2++) {
            c[j2][0] *= al0; c[j2][1] *= al0;
            c[j2][2] *= al1; c[j2][3] *= al1;
        }

        // ---- O += P * V (P c-frag -> a-frag via shuffles) ----
#pragma unroll
        for (int j = 0; j < 8; j++) {
            float v0 = __shfl_sync(0xffffffffu, sc[j][0], srcA);
            float v1 = __shfl_sync(0xffffffffu, sc[j][1], srcA);
            float v2 = __shfl_sync(0xffffffffu, sc[j][2], srcA);
            float v3 = __shfl_sync(0xffffffffu, sc[j][3], srcA);
            float w0 = __shfl_sync(0xffffffffu, sc[j][0], srcB);
            float w1 = __shfl_sync(0xffffffffu, sc[j][1], srcB);
            float w2 = __shfl_sync(0xffffffffu, sc[j][2], srcB);
            float w3 = __shfl_sync(0xffffffffu, sc[j][3], srcB);
            uint32_t a0 = __float_as_uint(odd ? v1 : v0);
            uint32_t a1 = __float_as_uint(odd ? v3 : v2);
            uint32_t a2 = __float_as_uint(odd ? w1 : w0);
            uint32_t a3 = __float_as_uint(odd ? w3 : w2);
#pragma unroll
            for (int j2 = 0; j2 < 16; j2++) {
                uint32_t b0 = __float_as_uint(Vs[(8 * j + tig)     * VP + 8 * j2 + gid]);
                uint32_t b1 = __float_as_uint(Vs[(8 * j + tig + 4) * VP + 8 * j2 + gid]);
                mma_tf32(c[j2], a0, a1, a2, a3, b0, b1);
            }
        }
    }

    // ---- normalize + write ----
    float inv0 = 1.0f / l0, inv1 = 1.0f / l1;
    int row0 = qt * FQT + wq + gid;
#pragma unroll
    for (int j2 = 0; j2 < 16; j2++) {
        int col = h * HD + 8 * j2 + 2 * tig;
        *(float2*)&g_attn[((size_t)b * SL + row0) * DIM + col] =
            make_float2(c[j2][0] * inv0, c[j2][1] * inv0);
        *(float2*)&g_attn[((size_t)b * SL + row0 + 8) * DIM + col] =
            make_float2(c[j2][2] * inv1, c[j2][3] * inv1);
    }
}

// ---------------------------------------------------------------------------
extern "C" void kernel_launch(void* const* d_in, const int* in_sizes, int n_in,
                              void* d_out, int out_size) {
    const float* x    = (const float*)d_in[0];
    const float* wqkv = (const float*)d_in[1];
    const float* wo   = (const float*)d_in[2];
    const float* qnw  = (const float*)d_in[3];
    const float* knw  = (const float*)d_in[4];
    const float* fcos = (const float*)d_in[5];
    const float* fsin = (const float*)d_in[6];
    float* out = (float*)d_out;

    void *p_qkv = nullptr, *p_attn = nullptr;
    cudaGetSymbolAddress(&p_qkv,  g_qkv);
    cudaGetSymbolAddress(&p_attn, g_attn);

    cudaFuncSetAttribute(flash_tf32,
                         cudaFuncAttributeMaxDynamicSharedMemorySize,
                         FLASH_SMEM);

    // 1) QKV projection (tf32 tensor)
    sgemm_tf32<<<dim3(QKV_N / 128, MROWS / 128), 256>>>(
        x, wqkv, (float*)p_qkv, MROWS, QKV_N, DIM);

    // 2) RMSNorm + RoPE
    norm_rope<<<MROWS * 24, 128>>>(qnw, knw, fcos, fsin);

    // 3) Flash attention (tf32 tensor)
    flash_tf32<<<dim3(SL / FQT, NH, BB), 256, FLASH_SMEM>>>();

    // 4) Output projection (tf32 tensor)
    sgemm_tf32<<<dim3(DIM / 128, MROWS / 128), 256>>>(
        (const float*)p_attn, wo, out, MROWS, DIM, DIM);
}

// round 7
// speedup vs baseline: 4.1522x; 1.2281x over previous
#include <cuda_runtime.h>
#include <math.h>
#include <stdint.h>

#define DIM   2048
#define NH    16
#define NKV   4
#define HD    128
#define BB    2
#define SL    2048
#define MROWS (BB*SL)                 // 4096
#define QKV_N ((NH + 2*NKV)*HD)       // 3072

// ---------------- scratch (static device globals; no allocations) -----------
__device__ float g_qkv [MROWS * QKV_N];        // [m][3072] fp32
__device__ float g_q   [BB*NH *SL*HD];         // tf32 values
__device__ float g_k   [BB*NKV*SL*HD];         // tf32
__device__ float g_v   [BB*NKV*SL*HD];         // tf32
__device__ float g_attn[MROWS * DIM];          // tf32 (feeds O-proj A)
__device__ float g_xc  [MROWS * DIM];          // tf32 copy of x
__device__ float g_wqc [QKV_N * DIM];          // tf32 copy of wqkv
__device__ float g_woc [DIM   * DIM];          // tf32 copy of wo

__device__ __forceinline__ float to_tf32(float x) {
    float r;
    asm("cvt.rna.tf32.f32 %0, %1;" : "=f"(r) : "f"(x));
    return r;
}

__device__ __forceinline__ void mma_tf32(float c[4],
                                         uint32_t a0, uint32_t a1,
                                         uint32_t a2, uint32_t a3,
                                         uint32_t b0, uint32_t b1) {
    asm volatile(
        "mma.sync.aligned.m16n8k8.row.col.f32.tf32.tf32.f32 "
        "{%0,%1,%2,%3},{%4,%5,%6,%7},{%8,%9},{%0,%1,%2,%3};"
        : "+f"(c[0]), "+f"(c[1]), "+f"(c[2]), "+f"(c[3])
        : "r"(a0), "r"(a1), "r"(a2), "r"(a3), "r"(b0), "r"(b1));
}

__device__ __forceinline__ void cp16(float* smem, const float* g) {
    uint32_t s = (uint32_t)__cvta_generic_to_shared(smem);
    asm volatile("cp.async.cg.shared.global [%0], [%1], 16;"
                 :: "r"(s), "l"(g) : "memory");
}
#define CP_COMMIT() asm volatile("cp.async.commit_group;" ::: "memory")
#define CP_WAIT1()  asm volatile("cp.async.wait_group 1;"  ::: "memory")
#define CP_WAIT0()  asm volatile("cp.async.wait_group 0;"  ::: "memory")

// ---------------------------------------------------------------------------
// Elementwise fp32 -> tf32 convert (float4 grid-stride).
// ---------------------------------------------------------------------------
__global__ void conv_tf32(const float* __restrict__ src, float* __restrict__ dst,
                          int n4) {
    int i = blockIdx.x * blockDim.x + threadIdx.x;
    int stride = gridDim.x * blockDim.x;
    for (; i < n4; i += stride) {
        float4 v = ((const float4*)src)[i];
        v.x = to_tf32(v.x); v.y = to_tf32(v.y);
        v.z = to_tf32(v.z); v.w = to_tf32(v.w);
        ((float4*)dst)[i] = v;
    }
}

// ---------------------------------------------------------------------------
// C = A * B^T, tf32 mma, cp.async 2-stage pipeline. A,B pre-converted tf32.
// Tile 128x128, K-stage 32, [m][k] smem pitch 36.
// ---------------------------------------------------------------------------
#define GP      36
#define GSTG    (128 * GP)                    // floats per operand per stage
#define GEMM_SMEM (4 * GSTG * 4)              // 2 stages x (A+B) = 73728 B
#define AS(s,r,k) sm[((s) * 128 + (r)) * GP + (k)]
#define BS(s,r,k) sm[2 * GSTG + ((s) * 128 + (r)) * GP + (k)]

__global__ __launch_bounds__(256, 2)
void sgemm_tf32(const float* __restrict__ A, const float* __restrict__ B,
                float* __restrict__ C, int M, int N, int K) {
    extern __shared__ float sm[];

    const int tid  = threadIdx.x;
    const int lane = tid & 31;
    const int warp = tid >> 5;
    const int wm   = warp & 1;
    const int wn   = warp >> 1;
    const int gid  = lane >> 2;
    const int tig  = lane & 3;

    const int m0 = blockIdx.y * 128;
    const int n0 = blockIdx.x * 128;
    const float* Ab = A + (size_t)m0 * K;
    const float* Bb = B + (size_t)n0 * K;

    const int cr = tid >> 3;                  // 0..31 used as row block below
    const int ck = (tid & 7) << 2;            // 0,4,..,28

    float c[4][4][4] = {};
    const int nstage = K / 32;

    // prologue: stage 0
#pragma unroll
    for (int it = 0; it < 4; it++) {
        int r = cr + it * 32;
        cp16(&AS(0, r, ck), Ab + (size_t)r * K + ck);
        cp16(&BS(0, r, ck), Bb + (size_t)r * K + ck);
    }
    CP_COMMIT();

    for (int s = 0; s < nstage; s++) {
        const int buf = s & 1;
        if (s + 1 < nstage) {
            int k0 = (s + 1) * 32;
#pragma unroll
            for (int it = 0; it < 4; it++) {
                int r = cr + it * 32;
                cp16(&AS(buf ^ 1, r, ck), Ab + (size_t)r * K + k0 + ck);
                cp16(&BS(buf ^ 1, r, ck), Bb + (size_t)r * K + k0 + ck);
            }
            CP_COMMIT();
            CP_WAIT1();
        } else {
            CP_WAIT0();
        }
        __syncthreads();

#pragma unroll
        for (int kk = 0; kk < 32; kk += 8) {
            const int k_lo = kk + tig;
            const int k_hi = kk + tig + 4;

            uint32_t a[4][4], b[4][2];
#pragma unroll
            for (int f = 0; f < 4; f++) {
                int row = wm * 64 + f * 16 + gid;
                a[f][0] = __float_as_uint(AS(buf, row,     k_lo));
                a[f][1] = __float_as_uint(AS(buf, row + 8, k_lo));
                a[f][2] = __float_as_uint(AS(buf, row,     k_hi));
                a[f][3] = __float_as_uint(AS(buf, row + 8, k_hi));
            }
#pragma unroll
            for (int g = 0; g < 4; g++) {
                int col = wn * 32 + g * 8 + gid;
                b[g][0] = __float_as_uint(BS(buf, col, k_lo));
                b[g][1] = __float_as_uint(BS(buf, col, k_hi));
            }
#pragma unroll
            for (int f = 0; f < 4; f++)
#pragma unroll
                for (int g = 0; g < 4; g++)
                    mma_tf32(c[f][g], a[f][0], a[f][1], a[f][2], a[f][3],
                             b[g][0], b[g][1]);
        }
        __syncthreads();
    }

#pragma unroll
    for (int f = 0; f < 4; f++) {
        int row = m0 + wm * 64 + f * 16 + gid;
#pragma unroll
        for (int g = 0; g < 4; g++) {
            int col = n0 + wn * 32 + g * 8 + 2 * tig;
            *(float2*)&C[(size_t)row * N + col] =
                make_float2(c[f][g][0], c[f][g][1]);
            *(float2*)&C[(size_t)(row + 8) * N + col] =
                make_float2(c[f][g][2], c[f][g][3]);
        }
    }
}

// Variant epilogue: write tf32-converted (for QKV? no — QKV output feeds norm,
// fp32 kept). Single epilogue suffices.

// ---------------------------------------------------------------------------
// RMSNorm + RoPE, one warp per (token, head) vector; float4 per lane.
// RoPE pairs are adjacent so both pair elements live in the same float4.
// Outputs stored pre-converted to tf32.
// ---------------------------------------------------------------------------
__global__ __launch_bounds__(256)
void norm_rope(const float* __restrict__ qnw, const float* __restrict__ knw,
               const float* __restrict__ fcos, const float* __restrict__ fsin) {
    const int lane = threadIdx.x & 31;
    const int widx = blockIdx.x * 8 + (threadIdx.x >> 5);   // vector index
    const int hh = widx % 24;
    const int m  = widx / 24;
    const int b  = m / SL;
    const int s  = m % SL;
    const int d4 = lane * 4;

    float4 v = *(const float4*)&g_qkv[(size_t)m * QKV_N + hh * HD + d4];

    if (hh < 20) {
        float ssq = v.x * v.x + v.y * v.y + v.z * v.z + v.w * v.w;
#pragma unroll
        for (int o = 16; o > 0; o >>= 1)
            ssq += __shfl_xor_sync(0xffffffffu, ssq, o);
        float r = rsqrtf(ssq * (1.0f / HD) + 1.1920929e-07f);

        const float* w = (hh < NH) ? qnw : knw;
        float4 wv = *(const float4*)&w[d4];
        float x0 = v.x * r * wv.x, x1 = v.y * r * wv.y;
        float x2 = v.z * r * wv.z, x3 = v.w * r * wv.w;

        float4 fc = *(const float4*)&fcos[s * HD + d4];
        float4 fs = *(const float4*)&fsin[s * HD + d4];
        float4 o;
        o.x = to_tf32(x0 * fc.x - x1 * fs.x);
        o.y = to_tf32(x1 * fc.y + x0 * fs.y);
        o.z = to_tf32(x2 * fc.z - x3 * fs.z);
        o.w = to_tf32(x3 * fc.w + x2 * fs.w);

        if (hh < NH)
            *(float4*)&g_q[(((size_t)b * NH  + hh)      * SL + s) * HD + d4] = o;
        else
            *(float4*)&g_k[(((size_t)b * NKV + (hh-16)) * SL + s) * HD + d4] = o;
    } else {
        float4 o;
        o.x = to_tf32(v.x); o.y = to_tf32(v.y);
        o.z = to_tf32(v.z); o.w = to_tf32(v.w);
        *(float4*)&g_v[(((size_t)b * NKV + (hh-20)) * SL + s) * HD + d4] = o;
    }
}

// ---------------------------------------------------------------------------
// Flash attention, tf32 mma, cp.async double-buffered K/V.
// QT=128 (8 warps x 16 rows), KT=64. Q frags in registers.
// smem: Ks[2] 64x132 each, Vs[2] 64x136 each = 137216 B; Q staging aliases
// the two K buffers (128*132*4 = 67584 = 2*64*132*4 exactly).
// ---------------------------------------------------------------------------
#define FQT  128
#define FKT  64
#define KP   132
#define VP   136
#define KS_OFF(buf) ((buf) * FKT * KP)
#define VS_OFF(buf) (2 * FKT * KP + (buf) * FKT * VP)
#define FLASH_SMEM ((2 * FKT * KP + 2 * FKT * VP) * 4)   // 137216 B

__global__ __launch_bounds__(256)
void flash_tf32() {
    extern __shared__ float sm[];

    const int tid  = threadIdx.x;
    const int lane = tid & 31;
    const int warp = tid >> 5;
    const int gid  = lane >> 2;
    const int tig  = lane & 3;
    const int wq   = warp * 16;

    const int qt = blockIdx.x, h = blockIdx.y, b = blockIdx.z;
    const int kvh = h >> 2;

    const float* Qg = g_q + (((size_t)b * NH  + h  ) * SL + qt * FQT) * HD;
    const float* Kg = g_k + (((size_t)b * NKV + kvh) * SL) * HD;
    const float* Vg = g_v + (((size_t)b * NKV + kvh) * SL) * HD;

    const float qscale = 1.4426950408889634f * rsqrtf((float)HD);

    // ---- stage Q (aliases K buffers), read frags, then release ----
    float* Qb = sm;
#pragma unroll
    for (int it = 0; it < 16; it++) {
        int idx = tid + it * 256;               // 0..4095 float4 slots
        int r = idx >> 5, c = (idx & 31) << 2;
        float4 v = *(const float4*)(Qg + (size_t)r * HD + c);
        Qb[r * KP + c + 0] = to_tf32(v.x * qscale);
        Qb[r * KP + c + 1] = to_tf32(v.y * qscale);
        Qb[r * KP + c + 2] = to_tf32(v.z * qscale);
        Qb[r * KP + c + 3] = to_tf32(v.w * qscale);
    }
    __syncthreads();

    uint32_t qa[16][4];
#pragma unroll
    for (int ks = 0; ks < 16; ks++) {
        int base = (wq + gid) * KP + 8 * ks + tig;
        qa[ks][0] = __float_as_uint(Qb[base]);
        qa[ks][1] = __float_as_uint(Qb[base + 8 * KP]);
        qa[ks][2] = __float_as_uint(Qb[base + 4]);
        qa[ks][3] = __float_as_uint(Qb[base + 8 * KP + 4]);
    }
    __syncthreads();   // all warps done reading Q before cp.async overwrites

    float c[16][4] = {};
    float m0 = -INFINITY, m1 = -INFINITY, l0 = 0.0f, l1 = 0.0f;

    const int srcA = (gid << 2) + (tig >> 1);
    const int srcB = srcA + 2;
    const bool odd = (tig & 1) != 0;

    const int cr = tid >> 5;              // 0..7 row group for copies
    const int cc = (tid & 31) << 2;       // 0..124 col

    // prologue: kt = 0 into buf 0
#pragma unroll
    for (int it = 0; it < 8; it++) {
        int r = cr + it * 8;
        cp16(sm + KS_OFF(0) + r * KP + cc, Kg + (size_t)r * HD + cc);
        cp16(sm + VS_OFF(0) + r * VP + cc, Vg + (size_t)r * HD + cc);
    }
    CP_COMMIT();

    const int NKT = SL / FKT;
    for (int kt = 0; kt < NKT; kt++) {
        const int buf = kt & 1;
        if (kt + 1 < NKT) {
            const float* Kn = Kg + (size_t)(kt + 1) * FKT * HD;
            const float* Vn = Vg + (size_t)(kt + 1) * FKT * HD;
#pragma unroll
            for (int it = 0; it < 8; it++) {
                int r = cr + it * 8;
                cp16(sm + KS_OFF(buf ^ 1) + r * KP + cc, Kn + (size_t)r * HD + cc);
                cp16(sm + VS_OFF(buf ^ 1) + r * VP + cc, Vn + (size_t)r * HD + cc);
            }
            CP_COMMIT();
            CP_WAIT1();
        } else {
            CP_WAIT0();
        }
        __syncthreads();

        const float* Ks = sm + KS_OFF(buf);
        const float* Vs = sm + VS_OFF(buf);

        // ---- S = Q * K^T ----
        float sc[8][4] = {};
#pragma unroll
        for (int ks = 0; ks < 16; ks++) {
#pragma unroll
            for (int j = 0; j < 8; j++) {
                uint32_t b0 = __float_as_uint(Ks[(8 * j + gid) * KP + 8 * ks + tig]);
                uint32_t b1 = __float_as_uint(Ks[(8 * j + gid) * KP + 8 * ks + tig + 4]);
                mma_tf32(sc[j], qa[ks][0], qa[ks][1], qa[ks][2], qa[ks][3], b0, b1);
            }
        }

        // ---- online softmax ----
        float t0 = -INFINITY, t1 = -INFINITY;
#pragma unroll
        for (int j = 0; j < 8; j++) {
            t0 = fmaxf(t0, fmaxf(sc[j][0], sc[j][1]));
            t1 = fmaxf(t1, fmaxf(sc[j][2], sc[j][3]));
        }
        t0 = fmaxf(t0, __shfl_xor_sync(0xffffffffu, t0, 1));
        t0 = fmaxf(t0, __shfl_xor_sync(0xffffffffu, t0, 2));
        t1 = fmaxf(t1, __shfl_xor_sync(0xffffffffu, t1, 1));
        t1 = fmaxf(t1, __shfl_xor_sync(0xffffffffu, t1, 2));
        float mn0 = fmaxf(m0, t0), mn1 = fmaxf(m1, t1);
        float al0 = exp2f(m0 - mn0), al1 = exp2f(m1 - mn1);
        m0 = mn0; m1 = mn1;

        float s0 = 0.0f, s1 = 0.0f;
#pragma unroll
        for (int j = 0; j < 8; j++) {
            float p0 = exp2f(sc[j][0] - mn0);
            float p1 = exp2f(sc[j][1] - mn0);
            float p2 = exp2f(sc[j][2] - mn1);
            float p3 = exp2f(sc[j][3] - mn1);
            s0 += p0 + p1; s1 += p2 + p3;
            sc[j][0] = to_tf32(p0); sc[j][1] = to_tf32(p1);
            sc[j][2] = to_tf32(p2); sc[j][3] = to_tf32(p3);
        }
        s0 += __shfl_xor_sync(0xffffffffu, s0, 1);
        s0 += __shfl_xor_sync(0xffffffffu, s0, 2);
        s1 += __shfl_xor_sync(0xffffffffu, s1, 1);
        s1 += __shfl_xor_sync(0xffffffffu, s1, 2);
        l0 = l0 * al0 + s0;
        l1 = l1 * al1 + s1;

#pragma unroll
        for (int j2 = 0; j2 < 16; j2++) {
            c[j2][0] *= al0; c[j2][1] *= al0;
            c[j2][2] *= al1; c[j2][3] *= al1;
        }

        // ---- O += P * V ----
#pragma unroll
        for (int j = 0; j < 8; j++) {
            float v0 = __shfl_sync(0xffffffffu, sc[j][0], srcA);
            float v1 = __shfl_sync(0xffffffffu, sc[j][1], srcA);
            float v2 = __shfl_sync(0xffffffffu, sc[j][2], srcA);
            float v3 = __shfl_sync(0xffffffffu, sc[j][3], srcA);
            float w0 = __shfl_sync(0xffffffffu, sc[j][0], srcB);
            float w1 = __shfl_sync(0xffffffffu, sc[j][1], srcB);
            float w2 = __shfl_sync(0xffffffffu, sc[j][2], srcB);
            float w3 = __shfl_sync(0xffffffffu, sc[j][3], srcB);
            uint32_t a0 = __float_as_uint(odd ? v1 : v0);
            uint32_t a1 = __float_as_uint(odd ? v3 : v2);
            uint32_t a2 = __float_as_uint(odd ? w1 : w0);
            uint32_t a3 = __float_as_uint(odd ? w3 : w2);
#pragma unroll
            for (int j2 = 0; j2 < 16; j2++) {
                uint32_t b0 = __float_as_uint(Vs[(8 * j + tig)     * VP + 8 * j2 + gid]);
                uint32_t b1 = __float_as_uint(Vs[(8 * j + tig + 4) * VP + 8 * j2 + gid]);
                mma_tf32(c[j2], a0, a1, a2, a3, b0, b1);
            }
        }
        __syncthreads();   // compute done before next cp.async overwrites buf
    }

    // ---- normalize + write (tf32 — feeds O-proj A operand) ----
    float inv0 = 1.0f / l0, inv1 = 1.0f / l1;
    int row0 = qt * FQT + wq + gid;
#pragma unroll
    for (int j2 = 0; j2 < 16; j2++) {
        int col = h * HD + 8 * j2 + 2 * tig;
        *(float2*)&g_attn[((size_t)b * SL + row0) * DIM + col] =
            make_float2(to_tf32(c[j2][0] * inv0), to_tf32(c[j2][1] * inv0));
        *(float2*)&g_attn[((size_t)b * SL + row0 + 8) * DIM + col] =
            make_float2(to_tf32(c[j2][2] * inv1), to_tf32(c[j2][3] * inv1));
    }
}

// ---------------------------------------------------------------------------
extern "C" void kernel_launch(void* const* d_in, const int* in_sizes, int n_in,
                              void* d_out, int out_size) {
    const float* x    = (const float*)d_in[0];
    const float* wqkv = (const float*)d_in[1];
    const float* wo   = (const float*)d_in[2];
    const float* qnw  = (const float*)d_in[3];
    const float* knw  = (const float*)d_in[4];
    const float* fcos = (const float*)d_in[5];
    const float* fsin = (const float*)d_in[6];
    float* out = (float*)d_out;

    void *p_qkv, *p_attn, *p_xc, *p_wqc, *p_woc;
    cudaGetSymbolAddress(&p_qkv,  g_qkv);
    cudaGetSymbolAddress(&p_attn, g_attn);
    cudaGetSymbolAddress(&p_xc,   g_xc);
    cudaGetSymbolAddress(&p_wqc,  g_wqc);
    cudaGetSymbolAddress(&p_woc,  g_woc);

    cudaFuncSetAttribute(flash_tf32,
                         cudaFuncAttributeMaxDynamicSharedMemorySize, FLASH_SMEM);
    cudaFuncSetAttribute(sgemm_tf32,
                         cudaFuncAttributeMaxDynamicSharedMemorySize, GEMM_SMEM);

    // 0) pre-convert GEMM operands to tf32
    conv_tf32<<<1024, 256>>>(x,    (float*)p_xc,  MROWS * DIM   / 4);
    conv_tf32<<<1024, 256>>>(wqkv, (float*)p_wqc, QKV_N * DIM   / 4);
    conv_tf32<<<1024, 256>>>(wo,   (float*)p_woc, DIM   * DIM   / 4);

    // 1) QKV projection
    sgemm_tf32<<<dim3(QKV_N / 128, MROWS / 128), 256, GEMM_SMEM>>>(
        (const float*)p_xc, (const float*)p_wqc, (float*)p_qkv,
        MROWS, QKV_N, DIM);

    // 2) RMSNorm + RoPE (warp per vector)
    norm_rope<<<MROWS * 24 / 8, 256>>>(qnw, knw, fcos, fsin);

    // 3) Flash attention
    flash_tf32<<<dim3(SL / FQT, NH, BB), 256, FLASH_SMEM>>>();

    // 4) Output projection
    sgemm_tf32<<<dim3(DIM / 128, MROWS / 128), 256, GEMM_SMEM>>>(
        (const float*)p_attn, (const float*)p_woc, out, MROWS, DIM, DIM);
}

// round 9
// speedup vs baseline: 4.5350x; 1.0922x over previous
#include <cuda_runtime.h>
#include <math.h>
#include <stdint.h>

#define DIM   2048
#define NH    16
#define NKV   4
#define HD    128
#define BB    2
#define SL    2048
#define MROWS (BB*SL)                 // 4096
#define QKV_N ((NH + 2*NKV)*HD)       // 3072

// ---------------- scratch (static device globals; no allocations) -----------
__device__ float g_qkv [MROWS * QKV_N];        // fp32
__device__ float g_q   [BB*NH *SL*HD];         // tf32 values
__device__ float g_k   [BB*NKV*SL*HD];         // tf32
__device__ float g_v   [BB*NKV*SL*HD];         // tf32
__device__ float g_attn[MROWS * DIM];          // tf32
__device__ float g_xc  [MROWS * DIM];          // tf32 copy of x
__device__ float g_wqc [QKV_N * DIM];          // tf32 copy of wqkv
__device__ float g_woc [DIM   * DIM];          // tf32 copy of wo

__device__ __forceinline__ float to_tf32(float x) {
    float r;
    asm("cvt.rna.tf32.f32 %0, %1;" : "=f"(r) : "f"(x));
    return r;
}

__device__ __forceinline__ void mma_tf32(float c[4],
                                         uint32_t a0, uint32_t a1,
                                         uint32_t a2, uint32_t a3,
                                         uint32_t b0, uint32_t b1) {
    asm volatile(
        "mma.sync.aligned.m16n8k8.row.col.f32.tf32.tf32.f32 "
        "{%0,%1,%2,%3},{%4,%5,%6,%7},{%8,%9},{%0,%1,%2,%3};"
        : "+f"(c[0]), "+f"(c[1]), "+f"(c[2]), "+f"(c[3])
        : "r"(a0), "r"(a1), "r"(a2), "r"(a3), "r"(b0), "r"(b1));
}

// ldmatrix x4: each b32 element read as a b16 pair; thread t of tile i gets
// (row t/4, b32-col t%4) in reg i — exactly the mma.tf32 fragment layout.
__device__ __forceinline__ void ldsm4(uint32_t& r0, uint32_t& r1,
                                      uint32_t& r2, uint32_t& r3,
                                      uint32_t addr) {
    asm volatile("ldmatrix.sync.aligned.m8n8.x4.shared.b16 {%0,%1,%2,%3}, [%4];"
                 : "=r"(r0), "=r"(r1), "=r"(r2), "=r"(r3) : "r"(addr));
}

__device__ __forceinline__ void cp16(void* smem, const float* g) {
    uint32_t s = (uint32_t)__cvta_generic_to_shared(smem);
    asm volatile("cp.async.cg.shared.global [%0], [%1], 16;"
                 :: "r"(s), "l"(g) : "memory");
}
#define CP_COMMIT() asm volatile("cp.async.commit_group;" ::: "memory")
#define CP_WAIT1()  asm volatile("cp.async.wait_group 1;"  ::: "memory")
#define CP_WAIT0()  asm volatile("cp.async.wait_group 0;"  ::: "memory")

// ---------------------------------------------------------------------------
// Elementwise fp32 -> tf32 convert.
// ---------------------------------------------------------------------------
__global__ void conv_tf32(const float* __restrict__ src, float* __restrict__ dst,
                          int n4) {
    int i = blockIdx.x * blockDim.x + threadIdx.x;
    int stride = gridDim.x * blockDim.x;
    for (; i < n4; i += stride) {
        float4 v = ((const float4*)src)[i];
        v.x = to_tf32(v.x); v.y = to_tf32(v.y);
        v.z = to_tf32(v.z); v.w = to_tf32(v.w);
        ((float4*)dst)[i] = v;
    }
}

// ---------------------------------------------------------------------------
// C = A * B^T, tf32 mma.sync, 3-stage cp.async, ldmatrix fragment loads.
// Tile 128x128, K-chunk 32, [m][k] smem pitch 36 (conflict-free for LDSM).
// ---------------------------------------------------------------------------
#define GP      36
#define GSTG    (128 * GP)
#define GEMM_SMEM (6 * GSTG * 4)              // 3 stages x (A+B) = 110592 B

__global__ __launch_bounds__(256, 2)
void sgemm_tf32(const float* __restrict__ A, const float* __restrict__ B,
                float* __restrict__ C, int M, int N, int K) {
    extern __shared__ float sm[];
    const uint32_t sbase = (uint32_t)__cvta_generic_to_shared(sm);

    const int tid  = threadIdx.x;
    const int lane = tid & 31;
    const int warp = tid >> 5;
    const int wm   = warp & 1;
    const int wn   = warp >> 1;
    const int gid  = lane >> 2;
    const int tig  = lane & 3;
    const int l8   = lane & 7;
    const int g8   = lane >> 3;

    const int m0 = blockIdx.y * 128;
    const int n0 = blockIdx.x * 128;
    const float* Ab = A + (size_t)m0 * K;
    const float* Bb = B + (size_t)n0 * K;

    // loader mapping: 4 rows per thread per operand per fill
    const int fr = tid >> 3;
    const int ck = (tid & 7) << 2;

    // ldmatrix per-thread byte offsets within a stage
    // A frag: lanes 0-7 tile(rows r0..r0+7, k), 8-15 (+8 rows), 16-23 (k+4), 24-31 (+8,k+4)
    const uint32_t offA = (uint32_t)(((wm * 64 + l8 + (g8 & 1) * 8) * GP
                                      + (g8 >> 1) * 4) * 4);
    // B frag pair: lanes 0-7 (cols c0..c0+7, k), 8-15 (k+4), 16-23 (+8 cols, k), 24-31 (+8,k+4)
    const uint32_t offB = (uint32_t)(((wn * 32 + l8 + (g8 >> 1) * 8) * GP
                                      + (g8 & 1) * 4) * 4);
    const uint32_t baseA = sbase;
    const uint32_t baseB = sbase + 3u * GSTG * 4u;

    float c[4][4][4] = {};
    const int nch = K / 32;

#define G_FILL(buf, k0)                                                       \
    {                                                                         \
        float* As_ = sm + (buf) * GSTG;                                       \
        float* Bs_ = sm + 3 * GSTG + (buf) * GSTG;                            \
        _Pragma("unroll")                                                     \
        for (int i = 0; i < 4; i++) {                                         \
            int r = fr + i * 32;                                              \
            cp16(As_ + r * GP + ck, Ab + (size_t)r * K + (k0) + ck);          \
            cp16(Bs_ + r * GP + ck, Bb + (size_t)r * K + (k0) + ck);          \
        }                                                                     \
    }

    G_FILL(0, 0);  CP_COMMIT();
    G_FILL(1, 32); CP_COMMIT();

    for (int ch = 0; ch < nch; ch++) {
        const int buf = ch % 3;
        if (ch + 1 < nch) CP_WAIT1(); else CP_WAIT0();
        __syncthreads();

        const uint32_t sA = baseA + (uint32_t)buf * GSTG * 4u;
        const uint32_t sB = baseB + (uint32_t)buf * GSTG * 4u;

#pragma unroll
        for (int kk = 0; kk < 32; kk += 8) {
            uint32_t a[4][4], b[4][2];
#pragma unroll
            for (int f = 0; f < 4; f++)
                ldsm4(a[f][0], a[f][1], a[f][2], a[f][3],
                      sA + offA + (uint32_t)((f * 16 * GP + kk) * 4));
#pragma unroll
            for (int gp = 0; gp < 2; gp++)
                ldsm4(b[2 * gp][0], b[2 * gp][1], b[2 * gp + 1][0], b[2 * gp + 1][1],
                      sB + offB + (uint32_t)((gp * 16 * GP + kk) * 4));
#pragma unroll
            for (int f = 0; f < 4; f++)
#pragma unroll
                for (int g = 0; g < 4; g++)
                    mma_tf32(c[f][g], a[f][0], a[f][1], a[f][2], a[f][3],
                             b[g][0], b[g][1]);
        }

        if (ch + 2 < nch) { G_FILL((ch + 2) % 3, (ch + 2) * 32); CP_COMMIT(); }
    }

#pragma unroll
    for (int f = 0; f < 4; f++) {
        int row = m0 + wm * 64 + f * 16 + gid;
#pragma unroll
        for (int g = 0; g < 4; g++) {
            int col = n0 + wn * 32 + g * 8 + 2 * tig;
            *(float2*)&C[(size_t)row * N + col] =
                make_float2(c[f][g][0], c[f][g][1]);
            *(float2*)&C[(size_t)(row + 8) * N + col] =
                make_float2(c[f][g][2], c[f][g][3]);
        }
    }
}

// ---------------------------------------------------------------------------
// RMSNorm + RoPE, one warp per (token, head) vector; outputs tf32.
// ---------------------------------------------------------------------------
__global__ __launch_bounds__(256)
void norm_rope(const float* __restrict__ qnw, const float* __restrict__ knw,
               const float* __restrict__ fcos, const float* __restrict__ fsin) {
    const int lane = threadIdx.x & 31;
    const int widx = blockIdx.x * 8 + (threadIdx.x >> 5);
    const int hh = widx % 24;
    const int m  = widx / 24;
    const int b  = m / SL;
    const int s  = m % SL;
    const int d4 = lane * 4;

    float4 v = *(const float4*)&g_qkv[(size_t)m * QKV_N + hh * HD + d4];

    if (hh < 20) {
        float ssq = v.x * v.x + v.y * v.y + v.z * v.z + v.w * v.w;
#pragma unroll
        for (int o = 16; o > 0; o >>= 1)
            ssq += __shfl_xor_sync(0xffffffffu, ssq, o);
        float r = rsqrtf(ssq * (1.0f / HD) + 1.1920929e-07f);

        const float* w = (hh < NH) ? qnw : knw;
        float4 wv = *(const float4*)&w[d4];
        float x0 = v.x * r * wv.x, x1 = v.y * r * wv.y;
        float x2 = v.z * r * wv.z, x3 = v.w * r * wv.w;

        float4 fc = *(const float4*)&fcos[s * HD + d4];
        float4 fs = *(const float4*)&fsin[s * HD + d4];
        float4 o;
        o.x = to_tf32(x0 * fc.x - x1 * fs.x);
        o.y = to_tf32(x1 * fc.y + x0 * fs.y);
        o.z = to_tf32(x2 * fc.z - x3 * fs.z);
        o.w = to_tf32(x3 * fc.w + x2 * fs.w);

        if (hh < NH)
            *(float4*)&g_q[(((size_t)b * NH  + hh)      * SL + s) * HD + d4] = o;
        else
            *(float4*)&g_k[(((size_t)b * NKV + (hh-16)) * SL + s) * HD + d4] = o;
    } else {
        float4 o;
        o.x = to_tf32(v.x); o.y = to_tf32(v.y);
        o.z = to_tf32(v.z); o.w = to_tf32(v.w);
        *(float4*)&g_v[(((size_t)b * NKV + (hh-20)) * SL + s) * HD + d4] = o;
    }
}

// ---------------------------------------------------------------------------
// Flash attention, tf32 mma.sync + ldmatrix, cp.async double-buffered K/V.
// QT=128 (8 warps x 16 rows), KT=64. Q frags register-resident.
// ---------------------------------------------------------------------------
#define FQT  128
#define FKT  64
#define KP   132
#define VP   136
#define KS_OFF(buf) ((buf) * FKT * KP)
#define VS_OFF(buf) (2 * FKT * KP + (buf) * FKT * VP)
#define FLASH_SMEM ((2 * FKT * KP + 2 * FKT * VP) * 4)   // 137216 B

__global__ __launch_bounds__(256)
void flash_tf32() {
    extern __shared__ float sm[];
    const uint32_t sbase = (uint32_t)__cvta_generic_to_shared(sm);

    const int tid  = threadIdx.x;
    const int lane = tid & 31;
    const int warp = tid >> 5;
    const int gid  = lane >> 2;
    const int tig  = lane & 3;
    const int l8   = lane & 7;
    const int g8   = lane >> 3;
    const int wq   = warp * 16;

    const int qt = blockIdx.x, h = blockIdx.y, b = blockIdx.z;
    const int kvh = h >> 2;

    const float* Qg = g_q + (((size_t)b * NH  + h  ) * SL + qt * FQT) * HD;
    const float* Kg = g_k + (((size_t)b * NKV + kvh) * SL) * HD;
    const float* Vg = g_v + (((size_t)b * NKV + kvh) * SL) * HD;

    const float qscale = 1.4426950408889634f * rsqrtf((float)HD);

    // ---- stage Q (aliases the two K buffers), frag-load via ldmatrix ----
    float* Qb = sm;
#pragma unroll
    for (int it = 0; it < 16; it++) {
        int idx = tid + it * 256;
        int r = idx >> 5, c = (idx & 31) << 2;
        float4 v = *(const float4*)(Qg + (size_t)r * HD + c);
        Qb[r * KP + c + 0] = to_tf32(v.x * qscale);
        Qb[r * KP + c + 1] = to_tf32(v.y * qscale);
        Qb[r * KP + c + 2] = to_tf32(v.z * qscale);
        Qb[r * KP + c + 3] = to_tf32(v.w * qscale);
    }
    __syncthreads();

    // A-frag offset: lanes 0-7 rows wq.., 8-15 +8 rows, 16-23 k+4, 24-31 both
    const uint32_t offQ = (uint32_t)(((wq + l8 + (g8 & 1) * 8) * KP
                                      + (g8 >> 1) * 4) * 4);
    uint32_t qa[16][4];
#pragma unroll
    for (int ks = 0; ks < 16; ks++)
        ldsm4(qa[ks][0], qa[ks][1], qa[ks][2], qa[ks][3],
              sbase + offQ + (uint32_t)(8 * ks * 4));
    __syncthreads();   // Q reads done before cp.async overwrites the alias

    float c[16][4] = {};
    float m0 = -INFINITY, m1 = -INFINITY, l0 = 0.0f, l1 = 0.0f;

    const int srcA = (gid << 2) + (tig >> 1);
    const int srcB = srcA + 2;
    const bool odd = (tig & 1) != 0;

    const int cr = tid >> 5;
    const int cc = (tid & 31) << 2;

    // B-frag pair offset within K buffer: rows = key index
    const uint32_t offK = (uint32_t)(((l8 + (g8 >> 1) * 8) * KP
                                      + (g8 & 1) * 4) * 4);

#pragma unroll
    for (int it = 0; it < 8; it++) {
        int r = cr + it * 8;
        cp16(sm + KS_OFF(0) + r * KP + cc, Kg + (size_t)r * HD + cc);
        cp16(sm + VS_OFF(0) + r * VP + cc, Vg + (size_t)r * HD + cc);
    }
    CP_COMMIT();

    const int NKT = SL / FKT;
    for (int kt = 0; kt < NKT; kt++) {
        const int buf = kt & 1;
        if (kt + 1 < NKT) {
            const float* Kn = Kg + (size_t)(kt + 1) * FKT * HD;
            const float* Vn = Vg + (size_t)(kt + 1) * FKT * HD;
#pragma unroll
            for (int it = 0; it < 8; it++) {
                int r = cr + it * 8;
                cp16(sm + KS_OFF(buf ^ 1) + r * KP + cc, Kn + (size_t)r * HD + cc);
                cp16(sm + VS_OFF(buf ^ 1) + r * VP + cc, Vn + (size_t)r * HD + cc);
            }
            CP_COMMIT();
            CP_WAIT1();
        } else {
            CP_WAIT0();
        }
        __syncthreads();

        const uint32_t sK = sbase + (uint32_t)(KS_OFF(buf) * 4);
        const float* Vs = sm + VS_OFF(buf);

        // ---- S = Q * K^T (ldmatrix B frags) ----
        float sc[8][4] = {};
#pragma unroll
        for (int ks = 0; ks < 16; ks++) {
#pragma unroll
            for (int jp = 0; jp < 4; jp++) {
                uint32_t b0, b1, b2, b3;
                ldsm4(b0, b1, b2, b3,
                      sK + offK + (uint32_t)((jp * 16 * KP + 8 * ks) * 4));
                mma_tf32(sc[2 * jp],     qa[ks][0], qa[ks][1], qa[ks][2], qa[ks][3], b0, b1);
                mma_tf32(sc[2 * jp + 1], qa[ks][0], qa[ks][1], qa[ks][2], qa[ks][3], b2, b3);
            }
        }

        // ---- online softmax ----
        float t0 = -INFINITY, t1 = -INFINITY;
#pragma unroll
        for (int j = 0; j < 8; j++) {
            t0 = fmaxf(t0, fmaxf(sc[j][0], sc[j][1]));
            t1 = fmaxf(t1, fmaxf(sc[j][2], sc[j][3]));
        }
        t0 = fmaxf(t0, __shfl_xor_sync(0xffffffffu, t0, 1));
        t0 = fmaxf(t0, __shfl_xor_sync(0xffffffffu, t0, 2));
        t1 = fmaxf(t1, __shfl_xor_sync(0xffffffffu, t1, 1));
        t1 = fmaxf(t1, __shfl_xor_sync(0xffffffffu, t1, 2));
        float mn0 = fmaxf(m0, t0), mn1 = fmaxf(m1, t1);
        float al0 = exp2f(m0 - mn0), al1 = exp2f(m1 - mn1);
        m0 = mn0; m1 = mn1;

        float s0 = 0.0f, s1 = 0.0f;
#pragma unroll
        for (int j = 0; j < 8; j++) {
            float p0 = exp2f(sc[j][0] - mn0);
            float p1 = exp2f(sc[j][1] - mn0);
            float p2 = exp2f(sc[j][2] - mn1);
            float p3 = exp2f(sc[j][3] - mn1);
            s0 += p0 + p1; s1 += p2 + p3;
            sc[j][0] = to_tf32(p0); sc[j][1] = to_tf32(p1);
            sc[j][2] = to_tf32(p2); sc[j][3] = to_tf32(p3);
        }
        s0 += __shfl_xor_sync(0xffffffffu, s0, 1);
        s0 += __shfl_xor_sync(0xffffffffu, s0, 2);
        s1 += __shfl_xor_sync(0xffffffffu, s1, 1);
        s1 += __shfl_xor_sync(0xffffffffu, s1, 2);
        l0 = l0 * al0 + s0;
        l1 = l1 * al1 + s1;

#pragma unroll
        for (int j2 = 0; j2 < 16; j2++) {
            c[j2][0] *= al0; c[j2][1] *= al0;
            c[j2][2] *= al1; c[j2][3] *= al1;
        }

        // ---- O += P * V (P c-frag -> a-frag via shuffles; V scalar LDS) ----
#pragma unroll
        for (int j = 0; j < 8; j++) {
            float v0 = __shfl_sync(0xffffffffu, sc[j][0], srcA);
            float v1 = __shfl_sync(0xffffffffu, sc[j][1], srcA);
            float v2 = __shfl_sync(0xffffffffu, sc[j][2], srcA);
            float v3 = __shfl_sync(0xffffffffu, sc[j][3], srcA);
            float w0 = __shfl_sync(0xffffffffu, sc[j][0], srcB);
            float w1 = __shfl_sync(0xffffffffu, sc[j][1], srcB);
            float w2 = __shfl_sync(0xffffffffu, sc[j][2], srcB);
            float w3 = __shfl_sync(0xffffffffu, sc[j][3], srcB);
            uint32_t a0 = __float_as_uint(odd ? v1 : v0);
            uint32_t a1 = __float_as_uint(odd ? v3 : v2);
            uint32_t a2 = __float_as_uint(odd ? w1 : w0);
            uint32_t a3 = __float_as_uint(odd ? w3 : w2);
#pragma unroll
            for (int j2 = 0; j2 < 16; j2++) {
                uint32_t b0 = __float_as_uint(Vs[(8 * j + tig)     * VP + 8 * j2 + gid]);
                uint32_t b1 = __float_as_uint(Vs[(8 * j + tig + 4) * VP + 8 * j2 + gid]);
                mma_tf32(c[j2], a0, a1, a2, a3, b0, b1);
            }
        }
        __syncthreads();
    }

    // ---- normalize + write ----
    float inv0 = 1.0f / l0, inv1 = 1.0f / l1;
    int row0 = qt * FQT + wq + gid;
#pragma unroll
    for (int j2 = 0; j2 < 16; j2++) {
        int col = h * HD + 8 * j2 + 2 * tig;
        *(float2*)&g_attn[((size_t)b * SL + row0) * DIM + col] =
            make_float2(to_tf32(c[j2][0] * inv0), to_tf32(c[j2][1] * inv0));
        *(float2*)&g_attn[((size_t)b * SL + row0 + 8) * DIM + col] =
            make_float2(to_tf32(c[j2][2] * inv1), to_tf32(c[j2][3] * inv1));
    }
}

// ---------------------------------------------------------------------------
extern "C" void kernel_launch(void* const* d_in, const int* in_sizes, int n_in,
                              void* d_out, int out_size) {
    const float* x    = (const float*)d_in[0];
    const float* wqkv = (const float*)d_in[1];
    const float* wo   = (const float*)d_in[2];
    const float* qnw  = (const float*)d_in[3];
    const float* knw  = (const float*)d_in[4];
    const float* fcos = (const float*)d_in[5];
    const float* fsin = (const float*)d_in[6];
    float* out = (float*)d_out;

    void *p_qkv, *p_attn, *p_xc, *p_wqc, *p_woc;
    cudaGetSymbolAddress(&p_qkv,  g_qkv);
    cudaGetSymbolAddress(&p_attn, g_attn);
    cudaGetSymbolAddress(&p_xc,   g_xc);
    cudaGetSymbolAddress(&p_wqc,  g_wqc);
    cudaGetSymbolAddress(&p_woc,  g_woc);

    cudaFuncSetAttribute(flash_tf32,
                         cudaFuncAttributeMaxDynamicSharedMemorySize, FLASH_SMEM);
    cudaFuncSetAttribute(sgemm_tf32,
                         cudaFuncAttributeMaxDynamicSharedMemorySize, GEMM_SMEM);

    // 0) pre-convert GEMM operands to tf32
    conv_tf32<<<1024, 256>>>(x,    (float*)p_xc,  MROWS * DIM / 4);
    conv_tf32<<<1024, 256>>>(wqkv, (float*)p_wqc, QKV_N * DIM / 4);
    conv_tf32<<<1024, 256>>>(wo,   (float*)p_woc, DIM   * DIM / 4);

    // 1) QKV projection
    sgemm_tf32<<<dim3(QKV_N / 128, MROWS / 128), 256, GEMM_SMEM>>>(
        (const float*)p_xc, (const float*)p_wqc, (float*)p_qkv,
        MROWS, QKV_N, DIM);

    // 2) RMSNorm + RoPE
    norm_rope<<<MROWS * 24 / 8, 256>>>(qnw, knw, fcos, fsin);

    // 3) Flash attention
    flash_tf32<<<dim3(SL / FQT, NH, BB), 256, FLASH_SMEM>>>();

    // 4) Output projection
    sgemm_tf32<<<dim3(DIM / 128, MROWS / 128), 256, GEMM_SMEM>>>(
        (const float*)p_attn, (const float*)p_woc, out, MROWS, DIM, DIM);
}